// round 15
// baseline (speedup 1.0000x reference)
#include <cuda_runtime.h>
#include <cuda_bf16.h>
#include <cuda_fp16.h>
#include <stdint.h>

#define DI __device__ __forceinline__

namespace {
constexpr int Bn = 2, Cn = 128, Hn = 256, Wn = 256;
constexpr int NWIN = 128;   // B * 8 * 8 chess phases
constexpr int NT   = 1024;  // tokens per window (32x32)
constexpr int QKVN = 192;   // 32 q + 32 k + 128 v
constexpr float LOG2E = 1.4426950408889634f;
// fused gather+proj smem (halfs): sX [256][128], sW [128][192], s1 [256][66], bias
constexpr int GP_SX = 0;
constexpr int GP_SW = GP_SX + 256 * 128;        // 32768
constexpr int GP_S1 = GP_SW + 128 * QKVN;       // 57344
constexpr int GP_BIAS_H = GP_S1 + 256 * 66;     // 74240 (halfs)
constexpr int GP_SMEM = GP_BIAS_H * 2 + QKVN * 4;  // 149248 bytes
// attention: M=16/warp, q-tile 128, 64-key k-tiles, TRIPLE buffered, 3 CTAs/SM (R12)
constexpr int QSTR = 40;                    // padded row stride Q/K (80B, conflict-free)
constexpr int KB   = 64;                    // keys per k-tile
constexpr int NKB  = NT / KB;               // 16
constexpr int SQ_ELEMS = 128 * QSTR;        // 5120
constexpr int SK_ELEMS = KB * QSTR;         // 2560 per buffer
constexpr int SV_ELEMS = KB * 128;          // 8192 per buffer
constexpr int ATTN_SMEM_BYTES = (SQ_ELEMS + 3 * SK_ELEMS + 3 * SV_ELEMS) * 2;  // 74752
}

// Scratch (static device globals; no runtime allocation)
__device__ __align__(16) __half g_QKV[NWIN * NT * QKVN];  // f16 [win][tok][192]
__device__ __align__(16) __half g_OW [NWIN * NT * Cn];    // f16 [win][tok][c]
__device__ __align__(16) __half g_W  [Cn * QKVN];         // packed f16 weights [k][n]

// ---------------- helpers ----------------
DI uint32_t smem_u32(const void* p) { return (uint32_t)__cvta_generic_to_shared(p); }

DI void ldm_x4(uint32_t* d, uint32_t a) {
    asm volatile("ldmatrix.sync.aligned.m8n8.x4.shared.b16 {%0,%1,%2,%3}, [%4];"
                 : "=r"(d[0]), "=r"(d[1]), "=r"(d[2]), "=r"(d[3]) : "r"(a));
}
DI void ldm_x4t(uint32_t* d, uint32_t a) {
    asm volatile("ldmatrix.sync.aligned.m8n8.x4.trans.shared.b16 {%0,%1,%2,%3}, [%4];"
                 : "=r"(d[0]), "=r"(d[1]), "=r"(d[2]), "=r"(d[3]) : "r"(a));
}
// f16 in / f16 accumulate
DI void mma_f16(uint32_t* c, const uint32_t* a, const uint32_t* b) {
    asm volatile("mma.sync.aligned.m16n8k16.row.col.f16.f16.f16.f16 "
                 "{%0,%1}, {%2,%3,%4,%5}, {%6,%7}, {%0,%1};"
                 : "+r"(c[0]), "+r"(c[1])
                 : "r"(a[0]), "r"(a[1]), "r"(a[2]), "r"(a[3]), "r"(b[0]), "r"(b[1]));
}
DI uint32_t pack_f16(float lo, float hi) {
    uint32_t d;
    asm("cvt.rn.f16x2.f32 %0, %1, %2;" : "=r"(d) : "f"(hi), "f"(lo));
    return d;
}
DI uint32_t ex2_f16x2(uint32_t a) {
    uint32_t d;
    asm("ex2.approx.f16x2 %0, %1;" : "=r"(d) : "r"(a));
    return d;
}
DI uint32_t hadd2(uint32_t a, uint32_t b) {
    uint32_t d;
    asm("add.f16x2 %0, %1, %2;" : "=r"(d) : "r"(a), "r"(b));
    return d;
}
DI float hsum(uint32_t a) {
    float lo, hi;
    asm("{\n\t.reg .b16 l, h;\n\tmov.b32 {l, h}, %2;\n\t"
        "cvt.f32.f16 %0, l;\n\tcvt.f32.f16 %1, h;\n\t}"
        : "=f"(lo), "=f"(hi) : "r"(a));
    return lo + hi;
}
DI void unpack_f16(uint32_t a, float& lo, float& hi) {
    asm("{\n\t.reg .b16 l, h;\n\tmov.b32 {l, h}, %2;\n\t"
        "cvt.f32.f16 %0, l;\n\tcvt.f32.f16 %1, h;\n\t}"
        : "=f"(lo), "=f"(hi) : "r"(a));
}
DI void cp16(uint32_t dst_smem, const void* src) {
    asm volatile("cp.async.cg.shared.global [%0], [%1], 16;" :: "r"(dst_smem), "l"(src));
}
DI void cp_commit() { asm volatile("cp.async.commit_group;"); }
DI void cp_wait0()  { asm volatile("cp.async.wait_group 0;"); }
DI void cp_wait1()  { asm volatile("cp.async.wait_group 1;"); }

// ---------------- kernel 0: pack weights to f16 (Wq pre-scaled by log2(e)) ----------
__global__ void k_pack(const float* __restrict__ Wq, const float* __restrict__ Wk,
                       const float* __restrict__ Wv) {
    int idx = blockIdx.x * 256 + threadIdx.x;
    if (idx >= Cn * QKVN) return;
    int k = idx / QKVN, n = idx % QKVN;
    float v = (n < 32) ? Wq[n * Cn + k] * LOG2E
            : (n < 64) ? Wk[(n - 32) * Cn + k]
                       : Wv[(n - 64) * Cn + k];
    g_W[idx] = __float2half(v);
}

// ---------------- kernel 1: FUSED chess gather + QKV projection ----------------
// grid (32 i, 8 py, 2 b), 256 threads. Block handles image row h=i*8+py:
// all 256 w-pixels = 8 px-windows x 32 j-tokens -> M=256 GEMM rows. x read once,
// fully coalesced; no intermediate XT tensor.
__global__ __launch_bounds__(256, 1) void k_gproj(const float* __restrict__ x,
                                                  const float* __restrict__ bq,
                                                  const float* __restrict__ bk,
                                                  const float* __restrict__ bv) {
    extern __shared__ __align__(16) char smem[];
    __half* sm = (__half*)smem;
    __half* sX = sm + GP_SX;       // [256][128] swizzled (rows = px*32+j)
    __half* sW = sm + GP_SW;       // [128][192] swizzled
    __half* s1 = sm + GP_S1;       // [256][66] staging
    float* sBias = (float*)(sm + GP_BIAS_H);
    const int i = blockIdx.x, py = blockIdx.y, b = blockIdx.z;
    const int h = i * 8 + py;
    const int tid = threadIdx.x, lane = tid & 31, warp = tid >> 5;

    if (tid < 192)
        sBias[tid] = (tid < 32) ? bq[tid] * LOG2E : (tid < 64) ? bk[tid - 32] : bv[tid - 64];

    // weights via cp.async (f16, swizzled)
#pragma unroll
    for (int it = 0; it < 12; it++) {
        int idx = it * 256 + tid, r = idx / 24, ch = idx % 24;
        int pch = (ch & 24) | ((ch ^ r) & 7);
        cp16(smem_u32(sW + r * QKVN + pch * 8), g_W + r * QKVN + ch * 8);
    }
    cp_commit();

    // x staging + transpose into sX (two 64-channel chunks)
#pragma unroll
    for (int z = 0; z < 2; z++) {
        if (z) __syncthreads();   // s1 reuse
        const float* xr = x + (((size_t)(b * Cn + z * 64)) * Hn + h) * Wn;
#pragma unroll 8
        for (int c = 0; c < 64; c++)
            s1[tid * 66 + c] = __float2half(xr[(size_t)c * Hn * Wn + tid]);
        __syncthreads();
#pragma unroll
        for (int it = 0; it < 32; it++) {
            int pair = it * 8 + warp;
            int px = pair >> 5, j = pair & 31;
            int wcol = j * 8 + px;
            uint32_t val = *(const uint32_t*)(s1 + wcol * 66 + 2 * lane);
            int row = px * 32 + j;
            int colh = z * 64 + 2 * lane;
            int ch = colh >> 3;
            int pch = (ch & 8) | ((ch ^ row) & 7);
            *(uint32_t*)(sX + row * 128 + pch * 8 + (colh & 7)) = val;
        }
    }
    cp_wait0();
    __syncthreads();

    // GEMM: M=256 (warp owns 32 rows), N=192, K=128, f16 accumulate
    uint32_t acc[2][24][2];
#pragma unroll
    for (int mh = 0; mh < 2; mh++)
#pragma unroll
        for (int t = 0; t < 24; t++) { acc[mh][t][0] = 0u; acc[mh][t][1] = 0u; }

    const int m0 = warp * 32, mat = lane >> 3, rl = lane & 7;
    const uint32_t sXb = smem_u32(sX), sWb = smem_u32(sW);
#pragma unroll
    for (int kk = 0; kk < 8; kk++) {
        uint32_t a4[2][4];
#pragma unroll
        for (int mh = 0; mh < 2; mh++) {
            int r = m0 + mh * 16 + ((mat & 1) << 3) + rl;
            int ch = kk * 2 + (mat >> 1);
            int pch = (ch & 8) | ((ch ^ r) & 7);
            ldm_x4(a4[mh], sXb + (uint32_t)(r * 256 + pch * 16));
        }
#pragma unroll
        for (int nt = 0; nt < 12; nt++) {
            uint32_t b4[4];
            int r = kk * 16 + ((mat & 1) << 3) + rl;
            int ch = nt * 2 + (mat >> 1);
            int pch = (ch & 24) | ((ch ^ r) & 7);
            ldm_x4t(b4, sWb + (uint32_t)(r * 384 + pch * 16));
#pragma unroll
            for (int mh = 0; mh < 2; mh++) {
                mma_f16(acc[mh][2 * nt], a4[mh], b4);
                mma_f16(acc[mh][2 * nt + 1], a4[mh], b4 + 2);
            }
        }
    }

    // epilogue: add bias, store f16 to g_QKV[win][tok]
    const int gid = lane >> 2, tid4 = lane & 3;
    const int px = m0 >> 5;                 // whole warp stays in one px window
    const int win = b * 64 + py * 8 + px;
#pragma unroll
    for (int mh = 0; mh < 2; mh++) {
        int j = mh * 16 + gid;
        int tok = i * 32 + j;
        __half* gQ = g_QKV + ((size_t)win * NT + tok) * QKVN;
#pragma unroll
        for (int t = 0; t < 24; t++) {
            int col = t * 8 + tid4 * 2;
            uint32_t bias2 = pack_f16(sBias[col], sBias[col + 1]);
            *(uint32_t*)(gQ + col) = hadd2(acc[mh][t][0], bias2);
            *(uint32_t*)(gQ + (size_t)8 * QKVN + col) = hadd2(acc[mh][t][1], bias2);
        }
    }
}

// ---------------- kernel 2: flash attention, f16 accum, M=16/warp, triple buffer ----
// grid (8 q-tiles of 128, 128 wins), 256 threads = 8 warps, 3 CTAs/SM (73KB smem).
__global__ __launch_bounds__(256, 3) void k_attn() {
    extern __shared__ __align__(16) char smem[];
    __half* sQ = (__half*)smem;                 // [128][QSTR]
    __half* sK = sQ + SQ_ELEMS;                 // 3 x [KB][QSTR]
    __half* sV = sK + 3 * SK_ELEMS;             // 3 x [KB][128] swizzled
    const int win = blockIdx.y, q0 = blockIdx.x * 128;
    const int tid = threadIdx.x, lane = tid & 31, warp = tid >> 5;
    const int mat = lane >> 3, rl = lane & 7, gid = lane >> 2, tid4 = lane & 3;
    const __half* gRow = g_QKV + (size_t)win * NT * QKVN;

    // prologue: Q + K/V tile 0 (group 1), K/V tile 1 (group 2)
    {
#pragma unroll
        for (int it = 0; it < 2; it++) {
            int idx = it * 256 + tid, r = idx >> 2, ch = idx & 3;
            cp16(smem_u32(sQ + r * QSTR + ch * 8), gRow + (size_t)(q0 + r) * QKVN + ch * 8);
        }
        {
            int r = tid >> 2, ch = tid & 3;
            cp16(smem_u32(sK + r * QSTR + ch * 8), gRow + (size_t)r * QKVN + 32 + ch * 8);
        }
#pragma unroll
        for (int it = 0; it < 4; it++) {
            int idx = it * 256 + tid, r = idx >> 4, ch = idx & 15;
            int pch = (ch & 8) | ((ch ^ r) & 7);
            cp16(smem_u32(sV + r * 128 + pch * 8), gRow + (size_t)r * QKVN + 64 + ch * 8);
        }
        cp_commit();
        const __half* src = gRow + (size_t)KB * QKVN;
        {
            int r = tid >> 2, ch = tid & 3;
            cp16(smem_u32(sK + SK_ELEMS + r * QSTR + ch * 8), src + (size_t)r * QKVN + 32 + ch * 8);
        }
#pragma unroll
        for (int it = 0; it < 4; it++) {
            int idx = it * 256 + tid, r = idx >> 4, ch = idx & 15;
            int pch = (ch & 8) | ((ch ^ r) & 7);
            cp16(smem_u32(sV + SV_ELEMS + r * 128 + pch * 8), src + (size_t)r * QKVN + 64 + ch * 8);
        }
        cp_commit();
    }
    cp_wait1();          // Q + tile 0 complete; tile 1 may be in flight
    __syncthreads();

    // Q fragment for this warp's 16 rows
    uint32_t aQ[2][4];
    {
        uint32_t sQb = smem_u32(sQ);
        int r = warp * 16 + ((mat & 1) << 3) + rl;
        ldm_x4(aQ[0], sQb + (uint32_t)(r * (QSTR * 2) + (mat >> 1) * 16));
        ldm_x4(aQ[1], sQb + (uint32_t)(r * (QSTR * 2) + 32 + (mat >> 1) * 16));
    }

    uint32_t O[16][2];   // f16x2 accumulators = 32 regs
#pragma unroll
    for (int t = 0; t < 16; t++) { O[t][0] = 0u; O[t][1] = 0u; }
    float l0 = 0.f, l1 = 0.f;
    const uint32_t sKb = smem_u32(sK), sVb = smem_u32(sV);

    int buf = 0;   // buffer of tile kb
    int pt  = 2;   // buffer for tile kb+2
    for (int kb = 0; kb < NKB; kb++) {
        if (kb + 2 < NKB) {
            const __half* src = gRow + (size_t)((kb + 2) * KB) * QKVN;
            __half* dK = sK + pt * SK_ELEMS;
            __half* dV = sV + pt * SV_ELEMS;
            {
                int r = tid >> 2, ch = tid & 3;
                cp16(smem_u32(dK + r * QSTR + ch * 8), src + (size_t)r * QKVN + 32 + ch * 8);
            }
#pragma unroll
            for (int it = 0; it < 4; it++) {
                int idx = it * 256 + tid, r = idx >> 4, ch = idx & 15;
                int pch = (ch & 8) | ((ch ^ r) & 7);
                cp16(smem_u32(dV + r * 128 + pch * 8), src + (size_t)r * QKVN + 64 + ch * 8);
            }
            cp_commit();
        }

        const uint32_t kBase = sKb + buf * (SK_ELEMS * 2);
        const uint32_t vBase = sVb + buf * (SV_ELEMS * 2);
        uint32_t rs0 = 0u, rs1 = 0u;
#pragma unroll
        for (int g = 0; g < 4; g++) {
            uint32_t S[2][2] = {{0u, 0u}, {0u, 0u}};
#pragma unroll
            for (int ks = 0; ks < 2; ks++) {
                uint32_t b4[4];
                int r = g * 16 + ((mat >> 1) << 3) + rl;
                int ch = ks * 2 + (mat & 1);
                ldm_x4(b4, kBase + (uint32_t)(r * (QSTR * 2) + ch * 16));
                mma_f16(S[0], aQ[ks], b4);
                mma_f16(S[1], aQ[ks], b4 + 2);
            }
            uint32_t aP[4];
            aP[0] = ex2_f16x2(S[0][0]);
            aP[1] = ex2_f16x2(S[0][1]);
            aP[2] = ex2_f16x2(S[1][0]);
            aP[3] = ex2_f16x2(S[1][1]);
            rs0 = hadd2(rs0, hadd2(aP[0], aP[2]));
            rs1 = hadd2(rs1, hadd2(aP[1], aP[3]));
#pragma unroll
            for (int nt = 0; nt < 8; nt++) {
                uint32_t b4[4];
                int r = g * 16 + ((mat & 1) << 3) + rl;
                int ch = nt * 2 + (mat >> 1);
                int pch = (ch & 8) | ((ch ^ r) & 7);
                ldm_x4t(b4, vBase + (uint32_t)(r * 256 + pch * 16));
                mma_f16(O[2 * nt], aP, b4);
                mma_f16(O[2 * nt + 1], aP, b4 + 2);
            }
        }
        l0 += hsum(rs0);
        l1 += hsum(rs1);

        if (kb < NKB - 1) {
            if (kb <= NKB - 3) cp_wait1(); else cp_wait0();
            __syncthreads();
        }
        buf = (buf == 2) ? 0 : buf + 1;
        pt  = (pt == 2) ? 0 : pt + 1;
    }

    // row sums live across the lane quad
    l0 += __shfl_xor_sync(0xffffffffu, l0, 1);
    l0 += __shfl_xor_sync(0xffffffffu, l0, 2);
    l1 += __shfl_xor_sync(0xffffffffu, l1, 1);
    l1 += __shfl_xor_sync(0xffffffffu, l1, 2);
    float inv0 = 1.f / l0, inv1 = 1.f / l1;

    const int row = q0 + warp * 16 + gid;
    __half* gO = g_OW + (size_t)win * NT * Cn;
#pragma unroll
    for (int t = 0; t < 16; t++) {
        int col = t * 8 + tid4 * 2;
        float a, b;
        unpack_f16(O[t][0], a, b);
        *(uint32_t*)(gO + (size_t)row * Cn + col) = pack_f16(a * inv0, b * inv0);
        unpack_f16(O[t][1], a, b);
        *(uint32_t*)(gO + (size_t)(row + 8) * Cn + col) = pack_f16(a * inv1, b * inv1);
    }
}

// ---------------- kernel 3: chess reverse + gamma*out + x ----------------
__global__ __launch_bounds__(256) void k_scatter(const float* __restrict__ x,
                                                 const float* __restrict__ gamma,
                                                 float* __restrict__ out) {
    __shared__ __align__(16) __half s[256 * 66];
    const int h = blockIdx.x, b = blockIdx.y, c0 = blockIdx.z * 64;
    const int tid = threadIdx.x, warp = tid >> 5, lane = tid & 31;
    const int i = h >> 3, py = h & 7;
#pragma unroll
    for (int it = 0; it < 32; it++) {
        int pair = it * 8 + warp;
        int px = pair >> 5, j = pair & 31;
        int win = b * 64 + py * 8 + px;
        int tok = i * 32 + j;
        uint32_t v = *(const uint32_t*)(g_OW + ((size_t)(win * NT + tok) * Cn + c0 + 2 * lane));
        *(uint32_t*)(s + (j * 8 + px) * 66 + 2 * lane) = v;
    }
    __syncthreads();
    const float gm = gamma[0];
    const float* xr = x + ((size_t)(b * Cn + c0) * Hn + h) * Wn;
    float* orow = out + ((size_t)(b * Cn + c0) * Hn + h) * Wn;
#pragma unroll 8
    for (int c = 0; c < 64; c++) {
        float o = __half2float(s[tid * 66 + c]);
        orow[(size_t)c * Hn * Wn + tid] = gm * o + xr[(size_t)c * Hn * Wn + tid];
    }
}

// ---------------- launch ----------------
extern "C" void kernel_launch(void* const* d_in, const int* in_sizes, int n_in,
                              void* d_out, int out_size) {
    const float* x  = (const float*)d_in[0];
    const float* Wq = (const float*)d_in[1];
    const float* bq = (const float*)d_in[2];
    const float* Wk = (const float*)d_in[3];
    const float* bk = (const float*)d_in[4];
    const float* Wv = (const float*)d_in[5];
    const float* bv = (const float*)d_in[6];
    const float* gamma = (const float*)d_in[7];

    cudaFuncSetAttribute(k_gproj, cudaFuncAttributeMaxDynamicSharedMemorySize, GP_SMEM);
    cudaFuncSetAttribute(k_attn, cudaFuncAttributeMaxDynamicSharedMemorySize, ATTN_SMEM_BYTES);

    k_pack<<<(Cn * QKVN + 255) / 256, 256>>>(Wq, Wk, Wv);
    k_gproj<<<dim3(32, 8, Bn), 256, GP_SMEM>>>(x, bq, bk, bv);
    k_attn<<<dim3(8, NWIN), 256, ATTN_SMEM_BYTES>>>();
    k_scatter<<<dim3(Hn, Bn, 2), 256>>>(x, gamma, (float*)d_out);
}

// round 16
// speedup vs baseline: 1.1001x; 1.1001x over previous
#include <cuda_runtime.h>
#include <cuda_bf16.h>
#include <cuda_fp16.h>
#include <stdint.h>

#define DI __device__ __forceinline__

namespace {
constexpr int Bn = 2, Cn = 128, Hn = 256, Wn = 256;
constexpr int NWIN = 128;   // B * 8 * 8 chess phases
constexpr int NT   = 1024;  // tokens per window (32x32)
constexpr int QKVN = 192;   // 32 q + 32 k + 128 v
constexpr float LOG2E = 1.4426950408889634f;
// fused gather+proj smem (half offsets): sW [128][192], sX chunk [256][64], s1 [256][34]
constexpr int GP_SW = 0;
constexpr int GP_SX = GP_SW + 128 * QKVN;       // 24576
constexpr int GP_S1 = GP_SX + 256 * 64;         // 40960
constexpr int GP_BIAS_H = GP_S1 + 256 * 34;     // 49664 (halfs)
constexpr int GP_SMEM = GP_BIAS_H * 2 + QKVN * 4;  // 100096 bytes -> 2 CTAs/SM
// attention: M=16/warp, q-tile 128, 64-key k-tiles, TRIPLE buffered, 3 CTAs/SM (R12)
constexpr int QSTR = 40;                    // padded row stride Q/K (80B, conflict-free)
constexpr int KB   = 64;                    // keys per k-tile
constexpr int NKB  = NT / KB;               // 16
constexpr int SQ_ELEMS = 128 * QSTR;        // 5120
constexpr int SK_ELEMS = KB * QSTR;         // 2560 per buffer
constexpr int SV_ELEMS = KB * 128;          // 8192 per buffer
constexpr int ATTN_SMEM_BYTES = (SQ_ELEMS + 3 * SK_ELEMS + 3 * SV_ELEMS) * 2;  // 74752
}

// Scratch (static device globals; no runtime allocation)
__device__ __align__(16) __half g_QKV[NWIN * NT * QKVN];  // f16 [win][tok][192]
__device__ __align__(16) __half g_OW [NWIN * NT * Cn];    // f16 [win][tok][c]
__device__ __align__(16) __half g_W  [Cn * QKVN];         // packed f16 weights [k][n]

// ---------------- helpers ----------------
DI uint32_t smem_u32(const void* p) { return (uint32_t)__cvta_generic_to_shared(p); }

DI void ldm_x4(uint32_t* d, uint32_t a) {
    asm volatile("ldmatrix.sync.aligned.m8n8.x4.shared.b16 {%0,%1,%2,%3}, [%4];"
                 : "=r"(d[0]), "=r"(d[1]), "=r"(d[2]), "=r"(d[3]) : "r"(a));
}
DI void ldm_x4t(uint32_t* d, uint32_t a) {
    asm volatile("ldmatrix.sync.aligned.m8n8.x4.trans.shared.b16 {%0,%1,%2,%3}, [%4];"
                 : "=r"(d[0]), "=r"(d[1]), "=r"(d[2]), "=r"(d[3]) : "r"(a));
}
// f16 in / f16 accumulate
DI void mma_f16(uint32_t* c, const uint32_t* a, const uint32_t* b) {
    asm volatile("mma.sync.aligned.m16n8k16.row.col.f16.f16.f16.f16 "
                 "{%0,%1}, {%2,%3,%4,%5}, {%6,%7}, {%0,%1};"
                 : "+r"(c[0]), "+r"(c[1])
                 : "r"(a[0]), "r"(a[1]), "r"(a[2]), "r"(a[3]), "r"(b[0]), "r"(b[1]));
}
DI uint32_t pack_f16(float lo, float hi) {
    uint32_t d;
    asm("cvt.rn.f16x2.f32 %0, %1, %2;" : "=r"(d) : "f"(hi), "f"(lo));
    return d;
}
DI uint32_t ex2_f16x2(uint32_t a) {
    uint32_t d;
    asm("ex2.approx.f16x2 %0, %1;" : "=r"(d) : "r"(a));
    return d;
}
DI uint32_t hadd2(uint32_t a, uint32_t b) {
    uint32_t d;
    asm("add.f16x2 %0, %1, %2;" : "=r"(d) : "r"(a), "r"(b));
    return d;
}
DI float hsum(uint32_t a) {
    float lo, hi;
    asm("{\n\t.reg .b16 l, h;\n\tmov.b32 {l, h}, %2;\n\t"
        "cvt.f32.f16 %0, l;\n\tcvt.f32.f16 %1, h;\n\t}"
        : "=f"(lo), "=f"(hi) : "r"(a));
    return lo + hi;
}
DI void unpack_f16(uint32_t a, float& lo, float& hi) {
    asm("{\n\t.reg .b16 l, h;\n\tmov.b32 {l, h}, %2;\n\t"
        "cvt.f32.f16 %0, l;\n\tcvt.f32.f16 %1, h;\n\t}"
        : "=f"(lo), "=f"(hi) : "r"(a));
}
DI void cp16(uint32_t dst_smem, const void* src) {
    asm volatile("cp.async.cg.shared.global [%0], [%1], 16;" :: "r"(dst_smem), "l"(src));
}
DI void cp_commit() { asm volatile("cp.async.commit_group;"); }
DI void cp_wait0()  { asm volatile("cp.async.wait_group 0;"); }
DI void cp_wait1()  { asm volatile("cp.async.wait_group 1;"); }

// ---------------- kernel 0: pack weights to f16 (Wq pre-scaled by log2(e)) ----------
__global__ void k_pack(const float* __restrict__ Wq, const float* __restrict__ Wk,
                       const float* __restrict__ Wv) {
    int idx = blockIdx.x * 256 + threadIdx.x;
    if (idx >= Cn * QKVN) return;
    int k = idx / QKVN, n = idx % QKVN;
    float v = (n < 32) ? Wq[n * Cn + k] * LOG2E
            : (n < 64) ? Wk[(n - 32) * Cn + k]
                       : Wv[(n - 64) * Cn + k];
    g_W[idx] = __float2half(v);
}

// ---------------- kernel 1: FUSED chess gather + QKV projection (2 CTAs/SM) ---------
// grid (32 i, 8 py, 2 b), 256 threads. Block handles image row h=i*8+py:
// 256 w-pixels = 8 px-windows x 32 j-tokens -> M=256 GEMM rows. x read once, coalesced.
// GEMM K is chunked (2 x 64 channels); sX holds one chunk; acc persists in regs.
__global__ __launch_bounds__(256, 2) void k_gproj(const float* __restrict__ x,
                                                  const float* __restrict__ bq,
                                                  const float* __restrict__ bk,
                                                  const float* __restrict__ bv) {
    extern __shared__ __align__(16) char smem[];
    __half* sm = (__half*)smem;
    __half* sW = sm + GP_SW;       // [128][192] swizzled
    __half* sX = sm + GP_SX;       // [256][64] SW128 chunk
    __half* s1 = sm + GP_S1;       // [256][34] staging (32 channels)
    float* sBias = (float*)(sm + GP_BIAS_H);
    const int i = blockIdx.x, py = blockIdx.y, b = blockIdx.z;
    const int h = i * 8 + py;
    const int tid = threadIdx.x, lane = tid & 31, warp = tid >> 5;

    if (tid < 192)
        sBias[tid] = (tid < 32) ? bq[tid] * LOG2E : (tid < 64) ? bk[tid - 32] : bv[tid - 64];

    // weights via cp.async (f16, swizzled): 3072 cp16s
#pragma unroll
    for (int it = 0; it < 12; it++) {
        int idx = it * 256 + tid, r = idx / 24, ch = idx % 24;
        int pch = (ch & 24) | ((ch ^ r) & 7);
        cp16(smem_u32(sW + r * QKVN + pch * 8), g_W + r * QKVN + ch * 8);
    }
    cp_commit();

    uint32_t acc[2][24][2];   // f16x2: 96 regs
#pragma unroll
    for (int mh = 0; mh < 2; mh++)
#pragma unroll
        for (int t = 0; t < 24; t++) { acc[mh][t][0] = 0u; acc[mh][t][1] = 0u; }

    const int m0 = warp * 32, mat = lane >> 3, rl = lane & 7;
    const uint32_t sXb = smem_u32(sX), sWb = smem_u32(sW);

    for (int kc = 0; kc < 2; kc++) {
        // stage + transpose 64 channels in two 32-channel passes
#pragma unroll
        for (int zz = 0; zz < 2; zz++) {
            if (kc || zz) __syncthreads();   // s1/sX reuse safety
            const int c0 = kc * 64 + zz * 32;
            const float* xr = x + (((size_t)(b * Cn + c0)) * Hn + h) * Wn;
#pragma unroll 8
            for (int cc = 0; cc < 32; cc++)
                s1[tid * 34 + cc] = __float2half(xr[(size_t)cc * Hn * Wn + tid]);
            __syncthreads();
#pragma unroll
            for (int it2 = 0; it2 < 16; it2++) {
                int rr = it2 * 16 + warp * 2 + (lane >> 4);
                int px = rr >> 5, j = rr & 31;
                int wcol = j * 8 + px;
                uint32_t v = *(const uint32_t*)(s1 + wcol * 34 + 2 * (lane & 15));
                int col = zz * 32 + 2 * (lane & 15);
                int ch16 = col >> 3;
                int pch = (ch16 ^ (rr & 7)) & 7;
                *(uint32_t*)(sX + rr * 64 + pch * 8 + (col & 7)) = v;
            }
        }
        if (kc == 0) cp_wait0();   // weights ready before first GEMM
        __syncthreads();

        // GEMM over this 64-channel K-chunk
#pragma unroll
        for (int kk = 0; kk < 4; kk++) {
            uint32_t a4[2][4];
#pragma unroll
            for (int mh = 0; mh < 2; mh++) {
                int r = m0 + mh * 16 + ((mat & 1) << 3) + rl;
                int ch16 = kk * 2 + (mat >> 1);
                int pch = (ch16 ^ (r & 7)) & 7;
                ldm_x4(a4[mh], sXb + (uint32_t)(r * 128 + pch * 16));
            }
#pragma unroll
            for (int nt = 0; nt < 12; nt++) {
                uint32_t b4[4];
                int r = kc * 64 + kk * 16 + ((mat & 1) << 3) + rl;
                int ch = nt * 2 + (mat >> 1);
                int pch = (ch & 24) | ((ch ^ r) & 7);
                ldm_x4t(b4, sWb + (uint32_t)(r * 384 + pch * 16));
#pragma unroll
                for (int mh = 0; mh < 2; mh++) {
                    mma_f16(acc[mh][2 * nt], a4[mh], b4);
                    mma_f16(acc[mh][2 * nt + 1], a4[mh], b4 + 2);
                }
            }
        }
    }

    // epilogue: add bias, store f16 to g_QKV[win][tok] (layout verified in R15)
    const int gid = lane >> 2, tid4 = lane & 3;
    const int px = m0 >> 5;                 // whole warp stays in one px window
    const int win = b * 64 + py * 8 + px;
#pragma unroll
    for (int mh = 0; mh < 2; mh++) {
        int j = mh * 16 + gid;
        int tok = i * 32 + j;
        __half* gQ = g_QKV + ((size_t)win * NT + tok) * QKVN;
#pragma unroll
        for (int t = 0; t < 24; t++) {
            int col = t * 8 + tid4 * 2;
            uint32_t bias2 = pack_f16(sBias[col], sBias[col + 1]);
            *(uint32_t*)(gQ + col) = hadd2(acc[mh][t][0], bias2);
            *(uint32_t*)(gQ + (size_t)8 * QKVN + col) = hadd2(acc[mh][t][1], bias2);
        }
    }
}

// ---------------- kernel 2: flash attention, f16 accum, M=16/warp, triple buffer ----
// grid (8 q-tiles of 128, 128 wins), 256 threads = 8 warps, 3 CTAs/SM (73KB smem).
__global__ __launch_bounds__(256, 3) void k_attn() {
    extern __shared__ __align__(16) char smem[];
    __half* sQ = (__half*)smem;                 // [128][QSTR]
    __half* sK = sQ + SQ_ELEMS;                 // 3 x [KB][QSTR]
    __half* sV = sK + 3 * SK_ELEMS;             // 3 x [KB][128] swizzled
    const int win = blockIdx.y, q0 = blockIdx.x * 128;
    const int tid = threadIdx.x, lane = tid & 31, warp = tid >> 5;
    const int mat = lane >> 3, rl = lane & 7, gid = lane >> 2, tid4 = lane & 3;
    const __half* gRow = g_QKV + (size_t)win * NT * QKVN;

    // prologue: Q + K/V tile 0 (group 1), K/V tile 1 (group 2)
    {
#pragma unroll
        for (int it = 0; it < 2; it++) {
            int idx = it * 256 + tid, r = idx >> 2, ch = idx & 3;
            cp16(smem_u32(sQ + r * QSTR + ch * 8), gRow + (size_t)(q0 + r) * QKVN + ch * 8);
        }
        {
            int r = tid >> 2, ch = tid & 3;
            cp16(smem_u32(sK + r * QSTR + ch * 8), gRow + (size_t)r * QKVN + 32 + ch * 8);
        }
#pragma unroll
        for (int it = 0; it < 4; it++) {
            int idx = it * 256 + tid, r = idx >> 4, ch = idx & 15;
            int pch = (ch & 8) | ((ch ^ r) & 7);
            cp16(smem_u32(sV + r * 128 + pch * 8), gRow + (size_t)r * QKVN + 64 + ch * 8);
        }
        cp_commit();
        const __half* src = gRow + (size_t)KB * QKVN;
        {
            int r = tid >> 2, ch = tid & 3;
            cp16(smem_u32(sK + SK_ELEMS + r * QSTR + ch * 8), src + (size_t)r * QKVN + 32 + ch * 8);
        }
#pragma unroll
        for (int it = 0; it < 4; it++) {
            int idx = it * 256 + tid, r = idx >> 4, ch = idx & 15;
            int pch = (ch & 8) | ((ch ^ r) & 7);
            cp16(smem_u32(sV + SV_ELEMS + r * 128 + pch * 8), src + (size_t)r * QKVN + 64 + ch * 8);
        }
        cp_commit();
    }
    cp_wait1();          // Q + tile 0 complete; tile 1 may be in flight
    __syncthreads();

    // Q fragment for this warp's 16 rows
    uint32_t aQ[2][4];
    {
        uint32_t sQb = smem_u32(sQ);
        int r = warp * 16 + ((mat & 1) << 3) + rl;
        ldm_x4(aQ[0], sQb + (uint32_t)(r * (QSTR * 2) + (mat >> 1) * 16));
        ldm_x4(aQ[1], sQb + (uint32_t)(r * (QSTR * 2) + 32 + (mat >> 1) * 16));
    }

    uint32_t O[16][2];   // f16x2 accumulators = 32 regs
#pragma unroll
    for (int t = 0; t < 16; t++) { O[t][0] = 0u; O[t][1] = 0u; }
    float l0 = 0.f, l1 = 0.f;
    const uint32_t sKb = smem_u32(sK), sVb = smem_u32(sV);

    int buf = 0;   // buffer of tile kb
    int pt  = 2;   // buffer for tile kb+2
    for (int kb = 0; kb < NKB; kb++) {
        if (kb + 2 < NKB) {
            const __half* src = gRow + (size_t)((kb + 2) * KB) * QKVN;
            __half* dK = sK + pt * SK_ELEMS;
            __half* dV = sV + pt * SV_ELEMS;
            {
                int r = tid >> 2, ch = tid & 3;
                cp16(smem_u32(dK + r * QSTR + ch * 8), src + (size_t)r * QKVN + 32 + ch * 8);
            }
#pragma unroll
            for (int it = 0; it < 4; it++) {
                int idx = it * 256 + tid, r = idx >> 4, ch = idx & 15;
                int pch = (ch & 8) | ((ch ^ r) & 7);
                cp16(smem_u32(dV + r * 128 + pch * 8), src + (size_t)r * QKVN + 64 + ch * 8);
            }
            cp_commit();
        }

        const uint32_t kBase = sKb + buf * (SK_ELEMS * 2);
        const uint32_t vBase = sVb + buf * (SV_ELEMS * 2);
        uint32_t rs0 = 0u, rs1 = 0u;
#pragma unroll
        for (int g = 0; g < 4; g++) {
            uint32_t S[2][2] = {{0u, 0u}, {0u, 0u}};
#pragma unroll
            for (int ks = 0; ks < 2; ks++) {
                uint32_t b4[4];
                int r = g * 16 + ((mat >> 1) << 3) + rl;
                int ch = ks * 2 + (mat & 1);
                ldm_x4(b4, kBase + (uint32_t)(r * (QSTR * 2) + ch * 16));
                mma_f16(S[0], aQ[ks], b4);
                mma_f16(S[1], aQ[ks], b4 + 2);
            }
            uint32_t aP[4];
            aP[0] = ex2_f16x2(S[0][0]);
            aP[1] = ex2_f16x2(S[0][1]);
            aP[2] = ex2_f16x2(S[1][0]);
            aP[3] = ex2_f16x2(S[1][1]);
            rs0 = hadd2(rs0, hadd2(aP[0], aP[2]));
            rs1 = hadd2(rs1, hadd2(aP[1], aP[3]));
#pragma unroll
            for (int nt = 0; nt < 8; nt++) {
                uint32_t b4[4];
                int r = g * 16 + ((mat & 1) << 3) + rl;
                int ch = nt * 2 + (mat >> 1);
                int pch = (ch & 8) | ((ch ^ r) & 7);
                ldm_x4t(b4, vBase + (uint32_t)(r * 256 + pch * 16));
                mma_f16(O[2 * nt], aP, b4);
                mma_f16(O[2 * nt + 1], aP, b4 + 2);
            }
        }
        l0 += hsum(rs0);
        l1 += hsum(rs1);

        if (kb < NKB - 1) {
            if (kb <= NKB - 3) cp_wait1(); else cp_wait0();
            __syncthreads();
        }
        buf = (buf == 2) ? 0 : buf + 1;
        pt  = (pt == 2) ? 0 : pt + 1;
    }

    // row sums live across the lane quad
    l0 += __shfl_xor_sync(0xffffffffu, l0, 1);
    l0 += __shfl_xor_sync(0xffffffffu, l0, 2);
    l1 += __shfl_xor_sync(0xffffffffu, l1, 1);
    l1 += __shfl_xor_sync(0xffffffffu, l1, 2);
    float inv0 = 1.f / l0, inv1 = 1.f / l1;

    const int row = q0 + warp * 16 + gid;
    __half* gO = g_OW + (size_t)win * NT * Cn;
#pragma unroll
    for (int t = 0; t < 16; t++) {
        int col = t * 8 + tid4 * 2;
        float a, b;
        unpack_f16(O[t][0], a, b);
        *(uint32_t*)(gO + (size_t)row * Cn + col) = pack_f16(a * inv0, b * inv0);
        unpack_f16(O[t][1], a, b);
        *(uint32_t*)(gO + (size_t)(row + 8) * Cn + col) = pack_f16(a * inv1, b * inv1);
    }
}

// ---------------- kernel 3: chess reverse + gamma*out + x ----------------
__global__ __launch_bounds__(256) void k_scatter(const float* __restrict__ x,
                                                 const float* __restrict__ gamma,
                                                 float* __restrict__ out) {
    __shared__ __align__(16) __half s[256 * 66];
    const int h = blockIdx.x, b = blockIdx.y, c0 = blockIdx.z * 64;
    const int tid = threadIdx.x, warp = tid >> 5, lane = tid & 31;
    const int i = h >> 3, py = h & 7;
#pragma unroll
    for (int it = 0; it < 32; it++) {
        int pair = it * 8 + warp;
        int px = pair >> 5, j = pair & 31;
        int win = b * 64 + py * 8 + px;
        int tok = i * 32 + j;
        uint32_t v = *(const uint32_t*)(g_OW + ((size_t)(win * NT + tok) * Cn + c0 + 2 * lane));
        *(uint32_t*)(s + (j * 8 + px) * 66 + 2 * lane) = v;
    }
    __syncthreads();
    const float gm = gamma[0];
    const float* xr = x + ((size_t)(b * Cn + c0) * Hn + h) * Wn;
    float* orow = out + ((size_t)(b * Cn + c0) * Hn + h) * Wn;
#pragma unroll 8
    for (int c = 0; c < 64; c++) {
        float o = __half2float(s[tid * 66 + c]);
        orow[(size_t)c * Hn * Wn + tid] = gm * o + xr[(size_t)c * Hn * Wn + tid];
    }
}

// ---------------- launch ----------------
extern "C" void kernel_launch(void* const* d_in, const int* in_sizes, int n_in,
                              void* d_out, int out_size) {
    const float* x  = (const float*)d_in[0];
    const float* Wq = (const float*)d_in[1];
    const float* bq = (const float*)d_in[2];
    const float* Wk = (const float*)d_in[3];
    const float* bk = (const float*)d_in[4];
    const float* Wv = (const float*)d_in[5];
    const float* bv = (const float*)d_in[6];
    const float* gamma = (const float*)d_in[7];

    cudaFuncSetAttribute(k_gproj, cudaFuncAttributeMaxDynamicSharedMemorySize, GP_SMEM);
    cudaFuncSetAttribute(k_attn, cudaFuncAttributeMaxDynamicSharedMemorySize, ATTN_SMEM_BYTES);

    k_pack<<<(Cn * QKVN + 255) / 256, 256>>>(Wq, Wk, Wv);
    k_gproj<<<dim3(32, 8, Bn), 256, GP_SMEM>>>(x, bq, bk, bv);
    k_attn<<<dim3(8, NWIN), 256, ATTN_SMEM_BYTES>>>();
    k_scatter<<<dim3(Hn, Bn, 2), 256>>>(x, gamma, (float*)d_out);
}